// round 1
// baseline (speedup 1.0000x reference)
#include <cuda_runtime.h>
#include <math.h>

#define NB 32
#define CI 8
#define CO 8
#define KR 4
#define DI 16
#define DOUT 16
#define SS 32
#define NPIX 1024   // 32*32
#define PLANE (DOUT*NPIX)   // 16384

// ---------------- scratch (static device globals; no allocation) -------------
__device__ float g_pooled[NB*CO*2*PLANE];   // [b][o][2][d][u][v]  33.5 MB
__device__ float g_preroute[NB*CO*PLANE];   // [b][o][d][u][v]     16.8 MB
__device__ float g_gate[NB*CO*PLANE];       // [b][o][d][u][v]     16.8 MB
__device__ double g_part[2*CO*NB];          // BN partial sums
__device__ float g_bnab[2*CO];              // per-o BN affine (scale, offset)

// ---------------------------------------------------------------------------
// K1: fused conv_trans + value einsum + pooled(max/mean over m) + routing-pre
// grid (o=8, b=32), 512 threads, 182 KB dynamic smem
// ---------------------------------------------------------------------------
extern "C" __global__ void __launch_bounds__(512, 1)
k1_conv_route(const float* __restrict__ caps, const float* __restrict__ Wt,
              const float* __restrict__ bt, const float* __restrict__ Wv,
              const float* __restrict__ bv)
{
    extern __shared__ float sm[];
    float* s_caps  = sm;                    // 16*34*34 = 18496 (zero-padded input)
    float* s_w     = s_caps + DI*34*34;     // 8*16*144 = 18432 ([c][d][cin][3][3])
    float* s_votes = s_w + 8*16*144;        // 8*1024   = 8192
    float* s_wv    = s_votes + 8*NPIX;      // 256  Wv[o][m][c]
    float* s_bv    = s_wv + 256;            // 32
    float* s_bias  = s_bv + 32;             // 128

    const int o = blockIdx.x, b = blockIdx.y;
    const int tid = threadIdx.x;

    // load padded input image for this batch
    for (int idx = tid; idx < DI*1156; idx += 512) {
        int ch = idx / 1156, rem = idx % 1156;
        int r = rem / 34, cc = rem % 34;
        float v = 0.f;
        if (r >= 1 && r <= SS && cc >= 1 && cc <= SS)
            v = caps[((b*DI + ch)*SS + (r-1))*SS + (cc-1)];
        s_caps[idx] = v;
    }
    // weights for this o: out-channel (c*8+o)*16+d
    for (int idx = tid; idx < 8*16*144; idx += 512) {
        int cd = idx / 144, j = idx % 144;
        int c = cd >> 4, d = cd & 15;
        s_w[idx] = Wt[(((c*CO + o)*DOUT + d)*144) + j];
    }
    for (int idx = tid; idx < 128; idx += 512) {
        int c = idx >> 4, d = idx & 15;
        s_bias[idx] = bt[(c*CO + o)*DOUT + d];
    }
    for (int idx = tid; idx < 256; idx += 512) s_wv[idx] = Wv[o*256 + idx];
    if (tid < 32) s_bv[tid] = bv[o*32 + tid];
    __syncthreads();

    const int c  = tid >> 6;        // 0..7 (C_in channel of votes)
    const int t  = tid & 63;
    const int r  = t >> 1;          // output row 0..31
    const int cb = (t & 1) << 4;    // column base 0 or 16
    const int obase = b*CO + o;

    for (int d = 0; d < DOUT; d++) {
        // ---- Phase A: compute votes[c][*][*] for this d (3x3 conv over 16 ch)
        float bias = s_bias[c*16 + d];
        float acc[16];
        #pragma unroll
        for (int j = 0; j < 16; j++) acc[j] = bias;
        const float* wbase = s_w + (c*16 + d)*144;
        #pragma unroll 1
        for (int cin = 0; cin < DI; cin++) {
            const float* wc = wbase + cin*9;
            const float* xb = s_caps + cin*1156 + r*34 + cb;
            #pragma unroll
            for (int dy = 0; dy < 3; dy++) {
                const float* xr = xb + dy*34;
                float xx[18];
                #pragma unroll
                for (int j = 0; j < 18; j++) xx[j] = xr[j];
                float w0 = wc[dy*3+0], w1 = wc[dy*3+1], w2 = wc[dy*3+2];
                #pragma unroll
                for (int j = 0; j < 16; j++)
                    acc[j] += w0*xx[j] + w1*xx[j+1] + w2*xx[j+2];
            }
        }
        {
            float* vr = s_votes + c*NPIX + r*32 + cb;
            #pragma unroll
            for (int j = 0; j < 16; j++) vr[j] = acc[j];
        }
        __syncthreads();

        // ---- Phase B: per-pixel 32x8 matvec + pool + routing stats
        #pragma unroll
        for (int pp = 0; pp < 2; pp++) {
            int p = tid + pp*512;
            float v8[8];
            #pragma unroll
            for (int ci = 0; ci < 8; ci++) v8[ci] = s_votes[ci*NPIX + p];
            float vmax = -3.0e38f, vsum = 0.f;
            float meanc[8], rc[8], rmax = 0.f;
            #pragma unroll
            for (int c2 = 0; c2 < 8; c2++) {
                float v4[4];
                #pragma unroll
                for (int k = 0; k < 4; k++) {
                    int m = k*8 + c2;
                    float a = s_bv[m];
                    #pragma unroll
                    for (int ci = 0; ci < 8; ci++) a += s_wv[m*8 + ci]*v8[ci];
                    v4[k] = a;
                    vmax = fmaxf(vmax, a);
                    vsum += a;
                }
                float mu = 0.25f*((v4[0]+v4[1]) + (v4[2]+v4[3]));
                float d0 = v4[0]-mu, d1 = v4[1]-mu, d2 = v4[2]-mu, d3 = v4[3]-mu;
                float var = 0.25f*((d0*d0 + d1*d1) + (d2*d2 + d3*d3));
                float rr = rsqrtf(var);           // = 1/std
                meanc[c2] = mu; rc[c2] = rr;
                rmax = fmaxf(rmax, rr);
            }
            // atts = softmax(-log std) == (1/std)/sum(1/std); scaled by 1/rmax for range safety
            float inv = 1.f/rmax;
            float num = 0.f, den = 0.f;
            #pragma unroll
            for (int c2 = 0; c2 < 8; c2++) {
                float w = rc[c2]*inv;
                num += w*meanc[c2]; den += w;
            }
            float pre = num/den;
            g_pooled[(obase*2 + 0)*PLANE + d*NPIX + p] = vmax;
            g_pooled[(obase*2 + 1)*PLANE + d*NPIX + p] = vsum*(1.f/32.f);
            g_preroute[obase*PLANE + d*NPIX + p] = pre;
        }
        __syncthreads();
    }
}

// ---------------------------------------------------------------------------
// K2: spatial gate 3x3x3 conv (2ch -> 1, pad 1) + BN partial sums (fp64)
// grid (o=8, b=32), 512 threads, 166.5 KB dynamic smem
// ---------------------------------------------------------------------------
extern "C" __global__ void __launch_bounds__(512, 1)
k2_gate(const float* __restrict__ Ws)
{
    extern __shared__ float sp[];  // [2][18][34][34] zero-padded pooled
    __shared__ float s_ws[54];
    __shared__ double s_redA[16], s_redB[16];

    const int o = blockIdx.x, b = blockIdx.y;
    const int tid = threadIdx.x;
    const int obase = b*CO + o;

    if (tid < 54) s_ws[tid] = Ws[tid];
    for (int idx = tid; idx < 2*18*1156; idx += 512) {
        int ch = idx / 20808, rem = idx % 20808;
        int dd = rem / 1156, r2 = (rem % 1156)/34, cc = rem % 34;
        float v = 0.f;
        if (dd >= 1 && dd <= 16 && r2 >= 1 && r2 <= 32 && cc >= 1 && cc <= 32)
            v = g_pooled[(obase*2 + ch)*PLANE + (dd-1)*NPIX + (r2-1)*32 + (cc-1)];
        sp[idx] = v;
    }
    __syncthreads();

    const int d = tid >> 5, u = tid & 31;   // one output row per thread
    float acc[32];
    #pragma unroll
    for (int v = 0; v < 32; v++) acc[v] = 0.f;
    #pragma unroll 1
    for (int ch = 0; ch < 2; ch++) {
        #pragma unroll
        for (int kd = 0; kd < 3; kd++) {
            #pragma unroll
            for (int kh = 0; kh < 3; kh++) {
                const float* xr = sp + ch*20808 + (d+kd)*1156 + (u+kh)*34;
                float xx[34];
                #pragma unroll
                for (int j = 0; j < 34; j++) xx[j] = xr[j];
                const float* wp = s_ws + ch*27 + kd*9 + kh*3;
                float w0 = wp[0], w1 = wp[1], w2 = wp[2];
                #pragma unroll
                for (int v = 0; v < 32; v++)
                    acc[v] += w0*xx[v] + w1*xx[v+1] + w2*xx[v+2];
            }
        }
    }
    double s = 0.0, s2 = 0.0;
    float* gout = g_gate + obase*PLANE + tid*32;
    #pragma unroll
    for (int v = 0; v < 32; v++) {
        gout[v] = acc[v];
        double dv = (double)acc[v];
        s += dv; s2 += dv*dv;
    }
    // block-reduce the two doubles
    #pragma unroll
    for (int off = 16; off > 0; off >>= 1) {
        s  += __shfl_down_sync(0xffffffffu, s,  off);
        s2 += __shfl_down_sync(0xffffffffu, s2, off);
    }
    int w = tid >> 5;
    if ((tid & 31) == 0) { s_redA[w] = s; s_redB[w] = s2; }
    __syncthreads();
    if (tid < 32) {
        double a = (tid < 16) ? s_redA[tid] : 0.0;
        double bq = (tid < 16) ? s_redB[tid] : 0.0;
        #pragma unroll
        for (int off = 8; off > 0; off >>= 1) {
            a  += __shfl_down_sync(0xffffffffu, a,  off);
            bq += __shfl_down_sync(0xffffffffu, bq, off);
        }
        if (tid == 0) {
            g_part[o*NB + b] = a;
            g_part[CO*NB + o*NB + b] = bq;
        }
    }
}

// ---------------------------------------------------------------------------
// K2b: finalize BN stats into per-o affine
// ---------------------------------------------------------------------------
extern "C" __global__ void k2b_bn(const float* __restrict__ bng,
                                  const float* __restrict__ bnb)
{
    int o = threadIdx.x;
    if (o < CO) {
        double s = 0.0, s2 = 0.0;
        for (int b = 0; b < NB; b++) {
            s  += g_part[o*NB + b];
            s2 += g_part[CO*NB + o*NB + b];
        }
        double n = (double)NB * PLANE;
        double mu = s / n;
        double var = s2 / n - mu*mu;
        float rstd = (float)(1.0 / sqrt(var + 1e-5));
        float a = bng[0] * rstd;
        g_bnab[o] = a;
        g_bnab[CO + o] = bnb[0] - (float)mu * a;
    }
}

// ---------------------------------------------------------------------------
// K3: caps_next = (1+sigmoid(BN(g)))*preroute, then LayerNorm over (d,u,v),
// write out as [Cout, B, D, h, w]
// ---------------------------------------------------------------------------
extern "C" __global__ void __launch_bounds__(512)
k3_finalize(const float* __restrict__ lng, const float* __restrict__ lnb,
            float* __restrict__ out)
{
    __shared__ float s_red[16];
    const int o = blockIdx.x, b = blockIdx.y;
    const int tid = threadIdx.x;
    const int base = (b*CO + o)*PLANE;
    const float a = g_bnab[o], ofs = g_bnab[CO + o];

    float x[32];
    float s = 0.f;
    #pragma unroll
    for (int i = 0; i < 32; i++) {
        int idx = tid + i*512;
        float g = g_gate[base + idx];
        float z = g*a + ofs;
        float sg = 1.f / (1.f + expf(-z));
        float val = g_preroute[base + idx] * (1.f + sg);
        x[i] = val; s += val;
    }
    // reduce sum
    #pragma unroll
    for (int off = 16; off > 0; off >>= 1) s += __shfl_down_sync(0xffffffffu, s, off);
    int w = tid >> 5;
    if ((tid & 31) == 0) s_red[w] = s;
    __syncthreads();
    if (tid < 32) {
        float t = (tid < 16) ? s_red[tid] : 0.f;
        #pragma unroll
        for (int off = 8; off > 0; off >>= 1) t += __shfl_down_sync(0xffffffffu, t, off);
        if (tid == 0) s_red[0] = t;
    }
    __syncthreads();
    float m = s_red[0] * (1.f/16384.f);
    __syncthreads();

    float v = 0.f;
    #pragma unroll
    for (int i = 0; i < 32; i++) { float dd = x[i] - m; v += dd*dd; }
    #pragma unroll
    for (int off = 16; off > 0; off >>= 1) v += __shfl_down_sync(0xffffffffu, v, off);
    if ((tid & 31) == 0) s_red[w] = v;
    __syncthreads();
    if (tid < 32) {
        float t = (tid < 16) ? s_red[tid] : 0.f;
        #pragma unroll
        for (int off = 8; off > 0; off >>= 1) t += __shfl_down_sync(0xffffffffu, t, off);
        if (tid == 0) s_red[0] = t;
    }
    __syncthreads();
    float rstd = rsqrtf(s_red[0]*(1.f/16384.f) + 1e-5f);

    float* op = out + (o*NB + b)*PLANE;
    #pragma unroll
    for (int i = 0; i < 32; i++) {
        int idx = tid + i*512;
        op[idx] = (x[i] - m)*rstd*lng[idx] + lnb[idx];
    }
}

// ---------------------------------------------------------------------------
extern "C" void kernel_launch(void* const* d_in, const int* in_sizes, int n_in,
                              void* d_out, int out_size)
{
    const float* caps = (const float*)d_in[0];
    const float* Wt   = (const float*)d_in[1];
    const float* bt   = (const float*)d_in[2];
    const float* Wv   = (const float*)d_in[3];
    const float* bv   = (const float*)d_in[4];
    const float* Ws   = (const float*)d_in[5];
    const float* bng  = (const float*)d_in[6];
    const float* bnb  = (const float*)d_in[7];
    const float* lng  = (const float*)d_in[8];
    const float* lnb  = (const float*)d_in[9];
    float* out = (float*)d_out;

    const int smem1 = (DI*34*34 + 8*16*144 + 8*NPIX + 256 + 32 + 128) * 4; // 182144
    const int smem2 = (2*18*1156) * 4;                                      // 166464
    cudaFuncSetAttribute(k1_conv_route, cudaFuncAttributeMaxDynamicSharedMemorySize, smem1);
    cudaFuncSetAttribute(k2_gate,       cudaFuncAttributeMaxDynamicSharedMemorySize, smem2);

    dim3 grid(CO, NB);
    k1_conv_route<<<grid, 512, smem1>>>(caps, Wt, bt, Wv, bv);
    k2_gate<<<grid, 512, smem2>>>(Ws);
    k2b_bn<<<1, 32>>>(bng, bnb);
    k3_finalize<<<grid, 512>>>(lng, lnb, out);
}